// round 7
// baseline (speedup 1.0000x reference)
#include <cuda_runtime.h>
#include <math.h>

#define NB 4
#define NT 100
#define ND 256
#define NHW 256
#define NF 400
#define BN_EPS 1e-5

// ---------------- scratch (device globals; no allocations) ----------------
__device__ float  g_y[NF * ND * NHW];      // conv output [f][c][hw] fp32 (~100MB)
__device__ double g_scaled[ND], g_shiftd[ND];
__device__ double g_ctxd[NF * ND];         // ctx_f per frame (double)
__device__ double g_salphad[NF];           // sum_l alpha_l
__device__ double g_hxd[NB * ND];          // current hx (double)
__device__ double g_cxd[NB * ND];          // current cx (double)
__device__ double g_histd[NT * NB * ND];   // hx history

// ---------------- conv 3x3 SAME, 256->256, dumb + double accumulate --------
// one block per (frame, oc); 256 threads = 256 output pixels.
__global__ void __launch_bounds__(256) conv_kernel(const float* __restrict__ x,
                                                   const float* __restrict__ w,
                                                   const float* __restrict__ bias) {
    int f  = blockIdx.x >> 8;
    int oc = blockIdx.x & 255;
    int tid = threadIdx.x;
    int h  = tid >> 4;
    int ww = tid & 15;

    __shared__ float plane[256];
    __shared__ float wk[9];

    double acc = (double)bias[oc];
    const float* xf = x + (size_t)f * (ND * NHW);

    for (int ic = 0; ic < ND; ic++) {
        __syncthreads();
        plane[tid] = xf[ic * 256 + tid];
        if (tid < 9) wk[tid] = w[((size_t)oc * ND + ic) * 9 + tid];
        __syncthreads();
#pragma unroll
        for (int kh = 0; kh < 3; kh++) {
            int hh = h + kh - 1;
            if ((unsigned)hh >= 16u) continue;
#pragma unroll
            for (int kw = 0; kw < 3; kw++) {
                int cc = ww + kw - 1;
                if ((unsigned)cc >= 16u) continue;
                acc += (double)plane[hh * 16 + cc] * (double)wk[kh * 3 + kw];
            }
        }
    }
    g_y[(size_t)f * 65536 + oc * 256 + tid] = (float)acc;
}

// ---------------- BN stats (double) -> scale/shift per channel -------------
__global__ void __launch_bounds__(256) stats_kernel(const float* __restrict__ gamma,
                                                    const float* __restrict__ beta) {
    int c = blockIdx.x, tid = threadIdx.x;
    double s = 0.0, ss = 0.0;
    for (int i = tid; i < NF * 256; i += 256) {
        int f = i >> 8, d = i & 255;
        double v = (double)g_y[(size_t)f * 65536 + c * 256 + d];
        s += v;
        ss += v * v;
    }
    __shared__ double rs[256], rss[256];
    rs[tid] = s; rss[tid] = ss;
    __syncthreads();
    for (int st = 128; st > 0; st >>= 1) {
        if (tid < st) { rs[tid] += rs[tid + st]; rss[tid] += rss[tid + st]; }
        __syncthreads();
    }
    if (tid == 0) {
        double n = (double)(NF * 256);
        double mu = rs[0] / n;
        double var = rss[0] / n - mu * mu;
        double rstd = 1.0 / sqrt(var + BN_EPS);
        double sc = (double)gamma[c] * rstd;
        g_scaled[c] = sc;
        g_shiftd[c] = (double)beta[c] - mu * sc;
    }
}

// ---------------- attention (double): alphas, logps (hx-independent) + ctx --
// feats[b,t,l,d]: l = CHANNEL, d = SPATIAL (raw reinterpret of (BT,C,H,W)).
__global__ void __launch_bounds__(256) attn_kernel(const float* __restrict__ wattn,
                                                   float* __restrict__ out) {
    int f = blockIdx.x, tid = threadIdx.x;
    int b = f / NT, t = f % NT;
    __shared__ double sc_s[256], sh_s[256], wa_s[256], alpha_s[256];
    __shared__ double wred[8];
    __shared__ double red[2];

    sc_s[tid] = g_scaled[tid];
    sh_s[tid] = g_shiftd[tid];
    wa_s[tid] = (double)wattn[tid];
    __syncthreads();

    // phase A: s[l] = sum_d relu(bn(y[f,l,d])) * wattn[d]
    const float* yrow = g_y + (size_t)f * 65536 + tid * 256;
    double scl = sc_s[tid], shl = sh_s[tid];
    double s = 0.0;
    for (int d = 0; d < 256; d++) {
        double fv = fmax((double)yrow[d] * scl + shl, 0.0);
        s += fv * wa_s[d];
    }

    // softmax over l (shift-invariant: hx-dependent constant dropped)
    double m = s;
#pragma unroll
    for (int o = 16; o; o >>= 1) m = fmax(m, __shfl_xor_sync(0xffffffffu, m, o));
    if ((tid & 31) == 0) wred[tid >> 5] = m;
    __syncthreads();
    if (tid == 0) {
        double mm = wred[0];
        for (int i = 1; i < 8; i++) mm = fmax(mm, wred[i]);
        red[0] = mm;
    }
    __syncthreads();
    double M = red[0];
    double e = exp(s - M);
    double z = e;
#pragma unroll
    for (int o = 16; o; o >>= 1) z += __shfl_xor_sync(0xffffffffu, z, o);
    if ((tid & 31) == 0) wred[tid >> 5] = z;
    __syncthreads();
    if (tid == 0) {
        double zz = 0.0;
        for (int i = 0; i < 8; i++) zz += wred[i];
        red[1] = zz;
    }
    __syncthreads();
    double Z = red[1];
    double alpha = e / Z;
    double lp = s - M - log(Z);

    int oidx = (t * NB + b) * 256 + tid;
    out[800 + oidx] = (float)alpha;       // alphas [T,B,L]
    out[103200 + oidx] = (float)lp;       // alpha_logps [T,B,L]
    alpha_s[tid] = alpha;
    __syncthreads();

    // salpha = sum_l alpha (actual fp value)
    double sa = alpha;
#pragma unroll
    for (int o = 16; o; o >>= 1) sa += __shfl_xor_sync(0xffffffffu, sa, o);
    if ((tid & 31) == 0) wred[tid >> 5] = sa;
    __syncthreads();
    if (tid == 0) {
        double s2 = 0.0;
        for (int i = 0; i < 8; i++) s2 += wred[i];
        g_salphad[f] = s2;
    }

    // phase C: ctx_f[d] = sum_l alpha[l]*feat[l,d]   (tid = d)
    const float* yf = g_y + (size_t)f * 65536;
    double acc = 0.0;
    for (int l = 0; l < 256; l++) {
        double fv = fmax((double)yf[l * 256 + tid] * sc_s[l] + sh_s[l], 0.0);
        acc += fv * alpha_s[l];
    }
    g_ctxd[f * 256 + tid] = acc;
}

// ---------------- initial hx/cx from frame-0 channel mean (double) ---------
__global__ void __launch_bounds__(256) init_kernel(const float* __restrict__ ihw,
                                                   const float* __restrict__ ihb,
                                                   const float* __restrict__ icw,
                                                   const float* __restrict__ icb) {
    int b = blockIdx.x, tid = threadIdx.x;
    __shared__ double x0[256], sc_s[256], sh_s[256];
    sc_s[tid] = g_scaled[tid];
    sh_s[tid] = g_shiftd[tid];
    __syncthreads();
    const float* yf = g_y + (size_t)(b * NT) * 65536;   // frame (b, t=0)
    double s = 0.0;
    for (int l = 0; l < 256; l++)
        s += fmax((double)yf[l * 256 + tid] * sc_s[l] + sh_s[l], 0.0);
    x0[tid] = s / 256.0;
    __syncthreads();
    double ah = (double)ihb[tid], ac = (double)icb[tid];
    for (int d = 0; d < 256; d++) {
        double xv = x0[d];
        ah += xv * (double)ihw[tid * 256 + d];
        ac += xv * (double)icw[tid * 256 + d];
    }
    g_hxd[b * 256 + tid] = tanh(ah);
    g_cxd[b * 256 + tid] = tanh(ac);
}

// ---------------- literal LSTM step (double, one launch per t) -------------
__global__ void __launch_bounds__(1024) step_kernel(int t,
                                                    const float* __restrict__ ww,
                                                    const float* __restrict__ wb,
                                                    const float* __restrict__ wih,
                                                    const float* __restrict__ whh,
                                                    const float* __restrict__ bih,
                                                    const float* __restrict__ bhh) {
    int b = blockIdx.x;
    int j = threadIdx.x;
    __shared__ double hx_s[256], ctx_s[256], gsm[1024];

    if (j < 256) hx_s[j] = g_hxd[b * 256 + j];
    __syncthreads();

    int f = b * NT + t;
    if (j < 256) {
        int d = j;
        double p = (double)wb[d];
        for (int k = 0; k < 256; k++)
            p += (double)ww[(size_t)d * 256 + k] * hx_s[k];
        ctx_s[d] = g_ctxd[f * 256 + d] + g_salphad[f] * p;
    }
    __syncthreads();

    double a = (double)bih[j] + (double)bhh[j];
    for (int k = 0; k < 256; k++) {
        a += (double)wih[(size_t)j * 256 + k] * ctx_s[k];
        a += (double)whh[(size_t)j * 256 + k] * hx_s[k];
    }
    gsm[j] = a;
    __syncthreads();

    if (j < 256) {
        int r = j;
        double gi = gsm[r], gf = gsm[256 + r], gg = gsm[512 + r], go = gsm[768 + r];
        double si = 1.0 / (1.0 + exp(-gi));
        double sf = 1.0 / (1.0 + exp(-gf));
        double so = 1.0 / (1.0 + exp(-go));
        double c = sf * g_cxd[b * 256 + r] + si * tanh(gg);
        g_cxd[b * 256 + r] = c;
        double h = so * tanh(c);
        g_hxd[b * 256 + r] = h;
        g_histd[t * 1024 + b * 256 + r] = h;
    }
}

// ---------------- preds[t,b,e] = hx_t @ wout^T + b (double) ----------------
__global__ void __launch_bounds__(256) preds_kernel(const float* __restrict__ woutw,
                                                    const float* __restrict__ woutb,
                                                    float* __restrict__ out) {
    int t = blockIdx.x, tid = threadIdx.x;
    if (tid >= 8) return;
    int b = tid >> 1, e = tid & 1;
    const double* hrow = g_histd + t * 1024 + b * 256;
    const float* wr = woutw + e * 256;
    double s = (double)woutb[e];
    for (int k = 0; k < 256; k++) s += hrow[k] * (double)wr[k];
    out[(t * 4 + b) * 2 + e] = (float)s;
}

// ---------------- launch ----------------
extern "C" void kernel_launch(void* const* d_in, const int* in_sizes, int n_in,
                              void* d_out, int out_size) {
    const float* cam    = (const float*)d_in[0];
    const float* convw  = (const float*)d_in[1];
    const float* convb  = (const float*)d_in[2];
    const float* gamma  = (const float*)d_in[3];
    const float* beta   = (const float*)d_in[4];
    const float* ihw    = (const float*)d_in[5];
    const float* ihb    = (const float*)d_in[6];
    const float* icw    = (const float*)d_in[7];
    const float* icb    = (const float*)d_in[8];
    const float* ww     = (const float*)d_in[9];
    const float* wb     = (const float*)d_in[10];
    const float* wattnw = (const float*)d_in[11];
    // d_in[12] = wattn_b : drops out of softmax/log_softmax (shift-invariant)
    const float* wih    = (const float*)d_in[13];
    const float* whh    = (const float*)d_in[14];
    const float* bih    = (const float*)d_in[15];
    const float* bhh    = (const float*)d_in[16];
    const float* woutw  = (const float*)d_in[17];
    const float* woutb  = (const float*)d_in[18];
    float* out = (float*)d_out;

    conv_kernel<<<NF * ND, 256>>>(cam, convw, convb);
    stats_kernel<<<ND, 256>>>(gamma, beta);
    attn_kernel<<<NF, 256>>>(wattnw, out);
    init_kernel<<<NB, 256>>>(ihw, ihb, icw, icb);
    for (int t = 0; t < NT; t++)
        step_kernel<<<NB, 1024>>>(t, ww, wb, wih, whh, bih, bhh);
    preds_kernel<<<NT, 256>>>(woutw, woutb, out);
}

// round 8
// speedup vs baseline: 30.6292x; 30.6292x over previous
#include <cuda_runtime.h>
#include <math.h>

#define NB 4
#define NT 100
#define ND 256
#define NHW 256
#define NF 400
#define BN_EPS 1e-5f

// ---------------- scratch (device globals; no allocations) ----------------
__device__ float g_y[NF * ND * NHW];     // conv output [f][c][hw]  (~100MB)
__device__ float g_scale[ND], g_shift[ND];
__device__ float g_ctx[NF * ND];         // ctx_f per frame
__device__ float g_G1[NF * 4 * ND];      // precomputed gate bias terms
__device__ float g_Weff[4 * ND * ND];    // Wih@w_w + Whh
__device__ float g_hx[NB * ND];          // current hx
__device__ float g_cx[NB * ND];          // current cx
__device__ float g_hist[NT * NB * ND];   // hx history for preds

// ---------------- conv 3x3 SAME, 256->256, fp32 direct ----------------
// grid: 400 frames * 8 oc-tiles of 32.  256 threads: og=tid&3 (8 oc each),
// q=tid>>2 -> (h, 4-wide w quad).  Per ic: smem input plane w/ halo + weights.
__global__ void __launch_bounds__(256) conv_kernel(const float* __restrict__ x,
                                                   const float* __restrict__ w,
                                                   const float* __restrict__ bias) {
    int f   = blockIdx.x >> 3;
    int oc0 = (blockIdx.x & 7) * 32;
    int tid = threadIdx.x;
    int og  = tid & 3;
    int q   = tid >> 2;          // 0..63
    int h   = q >> 2;            // 0..15
    int wb  = (q & 3) * 4;       // 0,4,8,12

    __shared__ __align__(16) float in_s[18 * 18];
    __shared__ __align__(16) float w_s[32 * 12];

    float acc[8][4];
#pragma unroll
    for (int i = 0; i < 8; i++)
#pragma unroll
        for (int j2 = 0; j2 < 4; j2++) acc[i][j2] = 0.f;

    const float* xin = x + (size_t)f * (ND * NHW);

    for (int ic = 0; ic < ND; ic++) {
        __syncthreads();
        for (int i = tid; i < 324; i += 256) {
            int r = i / 18, c = i % 18;
            int gh = r - 1, gw = c - 1;
            float v = 0.f;
            if ((unsigned)gh < 16u && (unsigned)gw < 16u) v = xin[ic * 256 + gh * 16 + gw];
            in_s[i] = v;
        }
        // FIXED (was `if (tid < 288)` with 256 threads -> entries 256..287
        // never staged; oc 28..31 of every tile used stale smem => rel_err 0.25)
        for (int i = tid; i < 288; i += 256) {
            int ocl = i / 9, k = i % 9;
            w_s[ocl * 12 + k] = w[((size_t)(oc0 + ocl) * ND + ic) * 9 + k];
        }
        __syncthreads();

        float v[3][6];
#pragma unroll
        for (int dh = 0; dh < 3; dh++)
#pragma unroll
            for (int j2 = 0; j2 < 6; j2++) v[dh][j2] = in_s[(h + dh) * 18 + wb + j2];

#pragma unroll
        for (int ocg = 0; ocg < 8; ocg++) {
            int ocl = og * 8 + ocg;
            const float4* wp = (const float4*)&w_s[ocl * 12];
            float4 w0 = wp[0], w1 = wp[1], w2 = wp[2];
            float wk[9] = {w0.x, w0.y, w0.z, w0.w, w1.x, w1.y, w1.z, w1.w, w2.x};
#pragma unroll
            for (int li = 0; li < 4; li++) {
                float a = acc[ocg][li];
#pragma unroll
                for (int kh = 0; kh < 3; kh++)
#pragma unroll
                    for (int kw = 0; kw < 3; kw++) a += v[kh][li + kw] * wk[kh * 3 + kw];
                acc[ocg][li] = a;
            }
        }
    }

#pragma unroll
    for (int ocg = 0; ocg < 8; ocg++) {
        int oc = oc0 + og * 8 + ocg;
        float bi = bias[oc];
#pragma unroll
        for (int li = 0; li < 4; li++)
            g_y[(size_t)f * (ND * NHW) + oc * 256 + h * 16 + wb + li] = acc[ocg][li] + bi;
    }
}

// ---------------- BN stats -> scale/shift per channel (double accum) -------
__global__ void __launch_bounds__(256) stats_kernel(const float* __restrict__ gamma,
                                                    const float* __restrict__ beta) {
    int c = blockIdx.x, tid = threadIdx.x;
    double s = 0.0, ss = 0.0;
    for (int i = tid; i < NF * 256; i += 256) {
        int f = i >> 8, d = i & 255;
        double v = (double)g_y[(size_t)f * 65536 + c * 256 + d];
        s += v;
        ss += v * v;
    }
    __shared__ double rs[256], rss[256];
    rs[tid] = s; rss[tid] = ss;
    __syncthreads();
    for (int st = 128; st > 0; st >>= 1) {
        if (tid < st) { rs[tid] += rs[tid + st]; rss[tid] += rss[tid + st]; }
        __syncthreads();
    }
    if (tid == 0) {
        double n = (double)(NF * 256);
        double mu = rs[0] / n;
        double var = rss[0] / n - mu * mu;
        double rstd = 1.0 / sqrt(var + (double)BN_EPS);
        float sc = (float)((double)gamma[c] * rstd);
        g_scale[c] = sc;
        g_shift[c] = (float)((double)beta[c] - mu * (double)gamma[c] * rstd);
    }
}

// ---------------- attention: alphas, alpha_logps (hx-independent!) + ctx_f ----
// feats[b,t,l,d]: l = CHANNEL, d = SPATIAL (raw reinterpret of (BT,C,H,W)).
__global__ void __launch_bounds__(256) attn_kernel(const float* __restrict__ wattn,
                                                   float* __restrict__ out) {
    int f = blockIdx.x, tid = threadIdx.x;
    int b = f / NT, t = f % NT;
    __shared__ __align__(16) float sc_s[256], sh_s[256], wa_s[256], alpha_s[256];
    __shared__ float wred[8];
    __shared__ float red[2];

    sc_s[tid] = g_scale[tid];
    sh_s[tid] = g_shift[tid];
    wa_s[tid] = wattn[tid];
    __syncthreads();

    // phase A: s[l] = sum_d relu(bn(y[f,l,d])) * wattn[d]   (row-contiguous)
    const float4* y4 = (const float4*)(g_y + (size_t)f * 65536 + tid * 256);
    const float4* wa4 = (const float4*)wa_s;
    float scl = sc_s[tid], shl = sh_s[tid];
    float s = 0.f;
#pragma unroll 8
    for (int d4 = 0; d4 < 64; d4++) {
        float4 y = y4[d4], wa = wa4[d4];
        s += fmaxf(fmaf(y.x, scl, shl), 0.f) * wa.x;
        s += fmaxf(fmaf(y.y, scl, shl), 0.f) * wa.y;
        s += fmaxf(fmaf(y.z, scl, shl), 0.f) * wa.z;
        s += fmaxf(fmaf(y.w, scl, shl), 0.f) * wa.w;
    }

    // softmax over l (shift-invariant: hx-dependent constant dropped)
    float m = s;
#pragma unroll
    for (int o = 16; o; o >>= 1) m = fmaxf(m, __shfl_xor_sync(0xffffffffu, m, o));
    if ((tid & 31) == 0) wred[tid >> 5] = m;
    __syncthreads();
    if (tid == 0) {
        float mm = wred[0];
        for (int i = 1; i < 8; i++) mm = fmaxf(mm, wred[i]);
        red[0] = mm;
    }
    __syncthreads();
    float M = red[0];
    float e = expf(s - M);
    float z = e;
#pragma unroll
    for (int o = 16; o; o >>= 1) z += __shfl_xor_sync(0xffffffffu, z, o);
    if ((tid & 31) == 0) wred[tid >> 5] = z;
    __syncthreads();
    if (tid == 0) {
        float zz = 0.f;
        for (int i = 0; i < 8; i++) zz += wred[i];
        red[1] = zz;
    }
    __syncthreads();
    float Z = red[1];
    float alpha = e / Z;
    float lp = s - M - logf(Z);

    int oidx = (t * NB + b) * 256 + tid;
    out[800 + oidx] = alpha;          // alphas [T,B,L]
    out[103200 + oidx] = lp;          // alpha_logps [T,B,L]
    alpha_s[tid] = alpha;
    __syncthreads();

    // phase C: ctx_f[d] = sum_l alpha[l]*feat[l,d]  (coalesced over d)
    const float* yf = g_y + (size_t)f * 65536;
    float acc = 0.f;
    for (int l = 0; l < 256; l++) {
        float v = yf[l * 256 + tid];
        acc += fmaxf(fmaf(v, sc_s[l], sh_s[l]), 0.f) * alpha_s[l];
    }
    g_ctx[f * 256 + tid] = acc;
}

// ---------------- initial hx/cx from frame-0 channel mean ----------------
__global__ void __launch_bounds__(256) init_kernel(const float* __restrict__ ihw,
                                                   const float* __restrict__ ihb,
                                                   const float* __restrict__ icw,
                                                   const float* __restrict__ icb) {
    int b = blockIdx.x, tid = threadIdx.x;
    __shared__ float x0[256], sc_s[256], sh_s[256];
    sc_s[tid] = g_scale[tid];
    sh_s[tid] = g_shift[tid];
    __syncthreads();
    const float* yf = g_y + (size_t)(b * NT) * 65536;   // frame (b, t=0)
    float s = 0.f;
    for (int l = 0; l < 256; l++)
        s += fmaxf(fmaf(yf[l * 256 + tid], sc_s[l], sh_s[l]), 0.f);
    x0[tid] = s * (1.f / 256.f);
    __syncthreads();
    float ah = ihb[tid], ac = icb[tid];
    for (int d = 0; d < 256; d++) {
        float xv = x0[d];
        ah += xv * ihw[tid * 256 + d];
        ac += xv * icw[tid * 256 + d];
    }
    g_hx[b * 256 + tid] = tanhf(ah);
    g_cx[b * 256 + tid] = tanhf(ac);
}

// ---------------- Weff = Wih @ w_w + Whh  (1024x256) ----------------
__global__ void __launch_bounds__(256) weff_kernel(const float* __restrict__ wih,
                                                   const float* __restrict__ ww,
                                                   const float* __restrict__ whh) {
    int j0 = blockIdx.x * 4, tid = threadIdx.x;
    __shared__ float wr[4][256];
    for (int i = tid; i < 1024; i += 256)
        wr[i >> 8][i & 255] = wih[(j0 + (i >> 8)) * 256 + (i & 255)];
    __syncthreads();
    float a0 = whh[(j0 + 0) * 256 + tid];
    float a1 = whh[(j0 + 1) * 256 + tid];
    float a2 = whh[(j0 + 2) * 256 + tid];
    float a3 = whh[(j0 + 3) * 256 + tid];
    for (int d = 0; d < 256; d++) {
        float wv = ww[d * 256 + tid];
        a0 += wr[0][d] * wv;
        a1 += wr[1][d] * wv;
        a2 += wr[2][d] * wv;
        a3 += wr[3][d] * wv;
    }
    g_Weff[(j0 + 0) * 256 + tid] = a0;
    g_Weff[(j0 + 1) * 256 + tid] = a1;
    g_Weff[(j0 + 2) * 256 + tid] = a2;
    g_Weff[(j0 + 3) * 256 + tid] = a3;
}

// ---------------- G1 = (ctx_f + w_b) @ Wih^T + bih + bhh ----------------
__global__ void __launch_bounds__(1024) g1_kernel(const float* __restrict__ wih,
                                                  const float* __restrict__ wb,
                                                  const float* __restrict__ bih,
                                                  const float* __restrict__ bhh) {
    int f = blockIdx.x, j = threadIdx.x;
    __shared__ __align__(16) float cv[256];
    if (j < 256) cv[j] = g_ctx[f * 256 + j] + wb[j];
    __syncthreads();
    float a = bih[j] + bhh[j];
    const float4* w4 = (const float4*)(wih + (size_t)j * 256);
    const float4* c4 = (const float4*)cv;
#pragma unroll 8
    for (int d4 = 0; d4 < 64; d4++) {
        float4 w = w4[d4], c = c4[d4];
        a += w.x * c.x + w.y * c.y + w.z * c.z + w.w * c.w;
    }
    g_G1[f * 1024 + j] = a;
}

// ---------------- LSTM step: gates = G1[t] + hx @ Weff^T (per-t launch) ----
__global__ void __launch_bounds__(1024) step_kernel(int t) {
    int b = blockIdx.x;
    int j = threadIdx.x;
    __shared__ __align__(16) float hx_s[256];
    __shared__ float gsm[1024];

    if (j < 256) hx_s[j] = g_hx[b * 256 + j];
    __syncthreads();

    float a = g_G1[(b * NT + t) * 1024 + j];
    const float4* w4 = (const float4*)(g_Weff + (size_t)j * 256);
    const float4* h4 = (const float4*)hx_s;
#pragma unroll 8
    for (int k4 = 0; k4 < 64; k4++) {
        float4 w = w4[k4], h = h4[k4];
        a += w.x * h.x + w.y * h.y + w.z * h.z + w.w * h.w;
    }
    gsm[j] = a;
    __syncthreads();

    if (j < 256) {
        int r = j;
        float gi = gsm[r], gf = gsm[256 + r], gg = gsm[512 + r], go = gsm[768 + r];
        float si = 1.f / (1.f + expf(-gi));
        float sf = 1.f / (1.f + expf(-gf));
        float so = 1.f / (1.f + expf(-go));
        float c = sf * g_cx[b * 256 + r] + si * tanhf(gg);
        g_cx[b * 256 + r] = c;
        float h = so * tanhf(c);
        g_hx[b * 256 + r] = h;
        g_hist[t * 1024 + b * 256 + r] = h;
    }
}

// ---------------- preds[t,b,e] = hx_t @ wout^T + b ----------------
__global__ void __launch_bounds__(256) preds_kernel(const float* __restrict__ woutw,
                                                    const float* __restrict__ woutb,
                                                    float* __restrict__ out) {
    int t = blockIdx.x, tid = threadIdx.x;
    int pair = tid >> 5, lane = tid & 31;
    if (pair >= 8) return;
    int b = pair >> 1, e = pair & 1;
    const float* hrow = g_hist + t * 1024 + b * 256;
    const float* wr = woutw + e * 256;
    float s = 0.f;
    for (int k = lane; k < 256; k += 32) s += hrow[k] * wr[k];
#pragma unroll
    for (int o = 16; o; o >>= 1) s += __shfl_xor_sync(0xffffffffu, s, o);
    if (lane == 0) out[(t * 4 + b) * 2 + e] = s + woutb[e];
}

// ---------------- launch ----------------
extern "C" void kernel_launch(void* const* d_in, const int* in_sizes, int n_in,
                              void* d_out, int out_size) {
    const float* cam    = (const float*)d_in[0];
    const float* convw  = (const float*)d_in[1];
    const float* convb  = (const float*)d_in[2];
    const float* gamma  = (const float*)d_in[3];
    const float* beta   = (const float*)d_in[4];
    const float* ihw    = (const float*)d_in[5];
    const float* ihb    = (const float*)d_in[6];
    const float* icw    = (const float*)d_in[7];
    const float* icb    = (const float*)d_in[8];
    const float* ww     = (const float*)d_in[9];
    const float* wb     = (const float*)d_in[10];
    const float* wattnw = (const float*)d_in[11];
    // d_in[12] = wattn_b : drops out of softmax/log_softmax (shift-invariant)
    const float* wih    = (const float*)d_in[13];
    const float* whh    = (const float*)d_in[14];
    const float* bih    = (const float*)d_in[15];
    const float* bhh    = (const float*)d_in[16];
    const float* woutw  = (const float*)d_in[17];
    const float* woutb  = (const float*)d_in[18];
    float* out = (float*)d_out;

    conv_kernel<<<NF * 8, 256>>>(cam, convw, convb);
    stats_kernel<<<ND, 256>>>(gamma, beta);
    attn_kernel<<<NF, 256>>>(wattnw, out);
    init_kernel<<<NB, 256>>>(ihw, ihb, icw, icb);
    weff_kernel<<<ND, 256>>>(wih, ww, whh);
    g1_kernel<<<NF, 1024>>>(wih, wb, bih, bhh);
    for (int t = 0; t < NT; t++)
        step_kernel<<<NB, 1024>>>(t);
    preds_kernel<<<NT, 256>>>(woutw, woutb, out);
}

// round 9
// speedup vs baseline: 70.6552x; 2.3068x over previous
#include <cuda_runtime.h>
#include <cuda_bf16.h>
#include <math.h>

#define NB 4
#define NT 100
#define ND 256
#define NHW 256
#define NF 400
#define BN_EPS 1e-5f

// ---------------- scratch (device globals; no allocations) ----------------
__device__ float g_y[NF * ND * NHW];     // conv output [f][oc][hw]  (~100MB)
__device__ unsigned int g_Apack[589824]; // packed bf16 hi/lo weight fragments (2.36MB)
__device__ float g_scale[ND], g_shift[ND];
__device__ float g_ctx[NF * ND];
__device__ float g_G1[NF * 4 * ND];
__device__ float g_Weff[4 * ND * ND];
__device__ float g_hx[NB * ND];
__device__ float g_cx[NB * ND];
__device__ float g_hist[NT * NB * ND];

// ======================= weight fragment pre-pack ==========================
// Apack idx = (((s*9+tap)*16 + icb)*16 + mt)*128 + lane*4 + j
// j: 0:(oc=g,   k=2q)  1:(oc=g+8, k=2q)  2:(oc=g, k=2q+8)  3:(oc=g+8, k=2q+8)
// word packs {split_s(W[oc][ic]), split_s(W[oc][ic+1])} (low half = even ic)
__global__ void __launch_bounds__(256) aprep_kernel(const float* __restrict__ w) {
    int idx = blockIdx.x * 256 + threadIdx.x;
    if (idx >= 589824) return;
    int j    = idx & 3;
    int lane = (idx >> 2) & 31;
    int mt   = (idx >> 7) & 15;
    int icb  = (idx >> 11) & 15;
    int rest = idx >> 15;            // s*9 + tap
    int tap  = rest % 9, s = rest / 9;
    int g = lane >> 2, q4 = lane & 3;
    int oc = mt * 16 + g + (j & 1) * 8;
    int qq = q4 + (j >> 1) * 4;
    int ic = icb * 16 + qq * 2;
    float w0 = w[((size_t)oc * 256 + ic) * 9 + tap];
    float w1 = w[((size_t)oc * 256 + ic + 1) * 9 + tap];
    __nv_bfloat162 v;
    if (s == 0) {
        v.x = __float2bfloat16(w0);
        v.y = __float2bfloat16(w1);
    } else {
        v.x = __float2bfloat16(w0 - __bfloat162float(__float2bfloat16(w0)));
        v.y = __float2bfloat16(w1 - __bfloat162float(__float2bfloat16(w1)));
    }
    g_Apack[idx] = *(unsigned int*)&v;
}

// ======================= conv as implicit GEMM (bf16x3 mma) ================
// Per frame: O[256 oc][256 hw] = W[256][2304] * P[2304][256], K = tap-major.
// CTA = (frame, oc-half of 128). 8 warps: (warp>>2) oc-tile of 64, (warp&3)
// hw-tile of 64.  smem: padded 18x18 planes, ic-pairs packed bf16x2, hi/lo,
// double-buffered in 16-ic chunks (one chunk = 9 k16 steps = the 9 taps).
#define MMA16816(d, a0_, a1_, a2_, a3_, b0_, b1_)                               \
    asm volatile(                                                               \
        "mma.sync.aligned.m16n8k16.row.col.f32.bf16.bf16.f32 "                  \
        "{%0,%1,%2,%3},{%4,%5,%6,%7},{%8,%9},{%0,%1,%2,%3};"                    \
        : "+f"(d[0]), "+f"(d[1]), "+f"(d[2]), "+f"(d[3])                        \
        : "r"(a0_), "r"(a1_), "r"(a2_), "r"(a3_), "r"(b0_), "r"(b1_))

__global__ void __launch_bounds__(256, 1) convmma_kernel(const float* __restrict__ x,
                                                         const float* __restrict__ bias) {
    __shared__ unsigned int bp[2][2][8][324];   // [buf][hi/lo][ic-pair][pix]

    int f    = blockIdx.x >> 1;
    int half = blockIdx.x & 1;
    int tid  = threadIdx.x;
    int lane = tid & 31, warp = tid >> 5;
    int g = lane >> 2, q4 = lane & 3;
    int hww = (warp & 3) * 64;

    const float* xf = x + (size_t)f * 65536;

    // zero the borders of all plane buffers (stays zero; staging writes interior only)
    for (int i = tid; i < 324; i += 256) {
        int r = i / 18, c = i % 18;
        if (r == 0 || r == 17 || c == 0 || c == 17) {
#pragma unroll
            for (int bu = 0; bu < 2; bu++)
#pragma unroll
                for (int s = 0; s < 2; s++)
#pragma unroll
                    for (int p = 0; p < 8; p++) bp[bu][s][p][i] = 0u;
        }
    }

    float acc[4][8][4];
#pragma unroll
    for (int mt = 0; mt < 4; mt++)
#pragma unroll
        for (int nt = 0; nt < 8; nt++)
#pragma unroll
            for (int r = 0; r < 4; r++) acc[mt][nt][r] = 0.f;

    int sp = tid >> 5;          // staging: ic-pair handled by this warp
    // stage chunk 0 into buf 0
    {
        const float* x0p = xf + (0 * 16 + sp * 2) * 256;
#pragma unroll
        for (int j = 0; j < 8; j++) {
            int px = (tid & 31) + j * 32;
            float v0 = x0p[px], v1 = x0p[256 + px];
            __nv_bfloat162 h, l;
            h.x = __float2bfloat16(v0); h.y = __float2bfloat16(v1);
            l.x = __float2bfloat16(v0 - __bfloat162float(h.x));
            l.y = __float2bfloat16(v1 - __bfloat162float(h.y));
            int pix = (px >> 4) * 18 + (px & 15) + 19;
            bp[0][0][sp][pix] = *(unsigned int*)&h;
            bp[0][1][sp][pix] = *(unsigned int*)&l;
        }
    }
    __syncthreads();

    // pixel-base per n-tile (row, col within 16x16)
    int rowb[8], colb[8];
#pragma unroll
    for (int nt = 0; nt < 8; nt++) {
        int n0 = hww + nt * 8;
        rowb[nt] = n0 >> 4;
        colb[nt] = n0 & 15;
    }

    for (int ch = 0; ch < 16; ch++) {
        int buf = ch & 1;
        if (ch < 15) {      // prefetch-stage next chunk into other buffer
            const float* x0p = xf + ((ch + 1) * 16 + sp * 2) * 256;
#pragma unroll
            for (int j = 0; j < 8; j++) {
                int px = (tid & 31) + j * 32;
                float v0 = x0p[px], v1 = x0p[256 + px];
                __nv_bfloat162 h, l;
                h.x = __float2bfloat16(v0); h.y = __float2bfloat16(v1);
                l.x = __float2bfloat16(v0 - __bfloat162float(h.x));
                l.y = __float2bfloat16(v1 - __bfloat162float(h.y));
                int pix = (px >> 4) * 18 + (px & 15) + 19;
                bp[buf ^ 1][0][sp][pix] = *(unsigned int*)&h;
                bp[buf ^ 1][1][sp][pix] = *(unsigned int*)&l;
            }
        }

        for (int tap = 0; tap < 9; tap++) {
            int dh = tap / 3, dw = tap % 3;
            // ---- B fragments: one LDS.32 each ----
            unsigned int bh0[8], bh1[8], bl0[8], bl1[8];
#pragma unroll
            for (int nt = 0; nt < 8; nt++) {
                int pix = (rowb[nt] + dh) * 18 + colb[nt] + dw + g;
                bh0[nt] = bp[buf][0][q4][pix];
                bh1[nt] = bp[buf][0][q4 + 4][pix];
                bl0[nt] = bp[buf][1][q4][pix];
                bl1[nt] = bp[buf][1][q4 + 4][pix];
            }
            // ---- A fragments: LDG.128, L2-hot ----
            uint4 ah[4], al[4];
#pragma unroll
            for (int mt = 0; mt < 4; mt++) {
                int mtg = half * 8 + (warp >> 2) * 4 + mt;
                ah[mt] = *(const uint4*)&g_Apack[(((0 * 9 + tap) * 16 + ch) * 16 + mtg) * 128 + lane * 4];
                al[mt] = *(const uint4*)&g_Apack[(((1 * 9 + tap) * 16 + ch) * 16 + mtg) * 128 + lane * 4];
            }
            // ---- 96 MMAs: Wh*Xh + Wh*Xl + Wl*Xh ----
#pragma unroll
            for (int mt = 0; mt < 4; mt++) {
#pragma unroll
                for (int nt = 0; nt < 8; nt++) {
                    MMA16816(acc[mt][nt], ah[mt].x, ah[mt].y, ah[mt].z, ah[mt].w, bh0[nt], bh1[nt]);
                    MMA16816(acc[mt][nt], ah[mt].x, ah[mt].y, ah[mt].z, ah[mt].w, bl0[nt], bl1[nt]);
                    MMA16816(acc[mt][nt], al[mt].x, al[mt].y, al[mt].z, al[mt].w, bh0[nt], bh1[nt]);
                }
            }
        }
        __syncthreads();
    }

    // ---- epilogue: bias + store fp32 [oc][hw] ----
    float* yout = g_y + (size_t)f * 65536;
#pragma unroll
    for (int mt = 0; mt < 4; mt++) {
        int oc = half * 128 + (warp >> 2) * 64 + mt * 16 + g;
        float b0v = bias[oc], b8v = bias[oc + 8];
#pragma unroll
        for (int nt = 0; nt < 8; nt++) {
            int hw = hww + nt * 8 + q4 * 2;
            float2 lo = make_float2(acc[mt][nt][0] + b0v, acc[mt][nt][1] + b0v);
            float2 hi = make_float2(acc[mt][nt][2] + b8v, acc[mt][nt][3] + b8v);
            *(float2*)&yout[oc * 256 + hw] = lo;
            *(float2*)&yout[(oc + 8) * 256 + hw] = hi;
        }
    }
}

// ---------------- BN stats -> scale/shift per channel (double accum) -------
__global__ void __launch_bounds__(256) stats_kernel(const float* __restrict__ gamma,
                                                    const float* __restrict__ beta) {
    int c = blockIdx.x, tid = threadIdx.x;
    double s = 0.0, ss = 0.0;
    for (int i = tid; i < NF * 256; i += 256) {
        int f = i >> 8, d = i & 255;
        double v = (double)g_y[(size_t)f * 65536 + c * 256 + d];
        s += v;
        ss += v * v;
    }
    __shared__ double rs[256], rss[256];
    rs[tid] = s; rss[tid] = ss;
    __syncthreads();
    for (int st = 128; st > 0; st >>= 1) {
        if (tid < st) { rs[tid] += rs[tid + st]; rss[tid] += rss[tid + st]; }
        __syncthreads();
    }
    if (tid == 0) {
        double n = (double)(NF * 256);
        double mu = rs[0] / n;
        double var = rss[0] / n - mu * mu;
        double rstd = 1.0 / sqrt(var + (double)BN_EPS);
        g_scale[c] = (float)((double)gamma[c] * rstd);
        g_shift[c] = (float)((double)beta[c] - mu * (double)gamma[c] * rstd);
    }
}

// ---------------- attention: alphas, alpha_logps (hx-independent!) + ctx_f ----
__global__ void __launch_bounds__(256) attn_kernel(const float* __restrict__ wattn,
                                                   float* __restrict__ out) {
    int f = blockIdx.x, tid = threadIdx.x;
    int b = f / NT, t = f % NT;
    __shared__ __align__(16) float sc_s[256], sh_s[256], wa_s[256], alpha_s[256];
    __shared__ float wred[8];
    __shared__ float red[2];

    sc_s[tid] = g_scale[tid];
    sh_s[tid] = g_shift[tid];
    wa_s[tid] = wattn[tid];
    __syncthreads();

    const float4* y4 = (const float4*)(g_y + (size_t)f * 65536 + tid * 256);
    const float4* wa4 = (const float4*)wa_s;
    float scl = sc_s[tid], shl = sh_s[tid];
    float s = 0.f;
#pragma unroll 8
    for (int d4 = 0; d4 < 64; d4++) {
        float4 y = y4[d4], wa = wa4[d4];
        s += fmaxf(fmaf(y.x, scl, shl), 0.f) * wa.x;
        s += fmaxf(fmaf(y.y, scl, shl), 0.f) * wa.y;
        s += fmaxf(fmaf(y.z, scl, shl), 0.f) * wa.z;
        s += fmaxf(fmaf(y.w, scl, shl), 0.f) * wa.w;
    }

    float m = s;
#pragma unroll
    for (int o = 16; o; o >>= 1) m = fmaxf(m, __shfl_xor_sync(0xffffffffu, m, o));
    if ((tid & 31) == 0) wred[tid >> 5] = m;
    __syncthreads();
    if (tid == 0) {
        float mm = wred[0];
        for (int i = 1; i < 8; i++) mm = fmaxf(mm, wred[i]);
        red[0] = mm;
    }
    __syncthreads();
    float M = red[0];
    float e = expf(s - M);
    float z = e;
#pragma unroll
    for (int o = 16; o; o >>= 1) z += __shfl_xor_sync(0xffffffffu, z, o);
    if ((tid & 31) == 0) wred[tid >> 5] = z;
    __syncthreads();
    if (tid == 0) {
        float zz = 0.f;
        for (int i = 0; i < 8; i++) zz += wred[i];
        red[1] = zz;
    }
    __syncthreads();
    float Z = red[1];
    float alpha = e / Z;
    float lp = s - M - logf(Z);

    int oidx = (t * NB + b) * 256 + tid;
    out[800 + oidx] = alpha;
    out[103200 + oidx] = lp;
    alpha_s[tid] = alpha;
    __syncthreads();

    const float* yf = g_y + (size_t)f * 65536;
    float acc = 0.f;
    for (int l = 0; l < 256; l++) {
        float v = yf[l * 256 + tid];
        acc += fmaxf(fmaf(v, sc_s[l], sh_s[l]), 0.f) * alpha_s[l];
    }
    g_ctx[f * 256 + tid] = acc;
}

// ---------------- initial hx/cx (coalesced warp-per-dot) ----------------
__global__ void __launch_bounds__(256) init_kernel(const float* __restrict__ ihw,
                                                   const float* __restrict__ ihb,
                                                   const float* __restrict__ icw,
                                                   const float* __restrict__ icb) {
    int b = blockIdx.x, tid = threadIdx.x;
    int lane = tid & 31, warp = tid >> 5;
    __shared__ float x0[256], sc_s[256], sh_s[256];
    sc_s[tid] = g_scale[tid];
    sh_s[tid] = g_shift[tid];
    __syncthreads();
    const float* yf = g_y + (size_t)(b * NT) * 65536;
    float s = 0.f;
    for (int l = 0; l < 256; l++)
        s += fmaxf(fmaf(yf[l * 256 + tid], sc_s[l], sh_s[l]), 0.f);
    x0[tid] = s * (1.f / 256.f);
    __syncthreads();
    for (int d0 = warp; d0 < 512; d0 += 8) {
        int j = d0 & 255, which = d0 >> 8;
        const float* wr = (which ? icw : ihw) + (size_t)j * 256;
        float a = 0.f;
        for (int k = lane; k < 256; k += 32) a += wr[k] * x0[k];
#pragma unroll
        for (int o = 16; o; o >>= 1) a += __shfl_xor_sync(0xffffffffu, a, o);
        if (lane == 0) {
            if (which) g_cx[b * 256 + j] = tanhf(a + icb[j]);
            else       g_hx[b * 256 + j] = tanhf(a + ihb[j]);
        }
    }
}

// ---------------- Weff = Wih @ w_w + Whh  (1024x256) ----------------
__global__ void __launch_bounds__(256) weff_kernel(const float* __restrict__ wih,
                                                   const float* __restrict__ ww,
                                                   const float* __restrict__ whh) {
    int j0 = blockIdx.x * 4, tid = threadIdx.x;
    __shared__ float wr[4][256];
    for (int i = tid; i < 1024; i += 256)
        wr[i >> 8][i & 255] = wih[(j0 + (i >> 8)) * 256 + (i & 255)];
    __syncthreads();
    float a0 = whh[(j0 + 0) * 256 + tid];
    float a1 = whh[(j0 + 1) * 256 + tid];
    float a2 = whh[(j0 + 2) * 256 + tid];
    float a3 = whh[(j0 + 3) * 256 + tid];
    for (int d = 0; d < 256; d++) {
        float wv = ww[d * 256 + tid];
        a0 += wr[0][d] * wv;
        a1 += wr[1][d] * wv;
        a2 += wr[2][d] * wv;
        a3 += wr[3][d] * wv;
    }
    g_Weff[(j0 + 0) * 256 + tid] = a0;
    g_Weff[(j0 + 1) * 256 + tid] = a1;
    g_Weff[(j0 + 2) * 256 + tid] = a2;
    g_Weff[(j0 + 3) * 256 + tid] = a3;
}

// ---------------- G1 = (ctx_f + w_b) @ Wih^T + bih + bhh ----------------
__global__ void __launch_bounds__(1024) g1_kernel(const float* __restrict__ wih,
                                                  const float* __restrict__ wb,
                                                  const float* __restrict__ bih,
                                                  const float* __restrict__ bhh) {
    int f = blockIdx.x, j = threadIdx.x;
    __shared__ __align__(16) float cv[256];
    if (j < 256) cv[j] = g_ctx[f * 256 + j] + wb[j];
    __syncthreads();
    float a = bih[j] + bhh[j];
    const float4* w4 = (const float4*)(wih + (size_t)j * 256);
    const float4* c4 = (const float4*)cv;
#pragma unroll 8
    for (int d4 = 0; d4 < 64; d4++) {
        float4 w = w4[d4], c = c4[d4];
        a += w.x * c.x + w.y * c.y + w.z * c.z + w.w * c.w;
    }
    g_G1[f * 1024 + j] = a;
}

// ---------------- LSTM step: gates = G1[t] + hx @ Weff^T (per-t launch) ----
__global__ void __launch_bounds__(1024) step_kernel(int t) {
    int b = blockIdx.x;
    int j = threadIdx.x;
    __shared__ __align__(16) float hx_s[256];
    __shared__ float gsm[1024];

    if (j < 256) hx_s[j] = g_hx[b * 256 + j];
    __syncthreads();

    float a = g_G1[(b * NT + t) * 1024 + j];
    const float4* w4 = (const float4*)(g_Weff + (size_t)j * 256);
    const float4* h4 = (const float4*)hx_s;
#pragma unroll 8
    for (int k4 = 0; k4 < 64; k4++) {
        float4 w = w4[k4], h = h4[k4];
        a += w.x * h.x + w.y * h.y + w.z * h.z + w.w * h.w;
    }
    gsm[j] = a;
    __syncthreads();

    if (j < 256) {
        int r = j;
        float gi = gsm[r], gf = gsm[256 + r], gg = gsm[512 + r], go = gsm[768 + r];
        float si = 1.f / (1.f + expf(-gi));
        float sf = 1.f / (1.f + expf(-gf));
        float so = 1.f / (1.f + expf(-go));
        float c = sf * g_cx[b * 256 + r] + si * tanhf(gg);
        g_cx[b * 256 + r] = c;
        float h = so * tanhf(c);
        g_hx[b * 256 + r] = h;
        g_hist[t * 1024 + b * 256 + r] = h;
    }
}

// ---------------- preds[t,b,e] = hx_t @ wout^T + b ----------------
__global__ void __launch_bounds__(256) preds_kernel(const float* __restrict__ woutw,
                                                    const float* __restrict__ woutb,
                                                    float* __restrict__ out) {
    int t = blockIdx.x, tid = threadIdx.x;
    int pair = tid >> 5, lane = tid & 31;
    if (pair >= 8) return;
    int b = pair >> 1, e = pair & 1;
    const float* hrow = g_hist + t * 1024 + b * 256;
    const float* wr = woutw + e * 256;
    float s = 0.f;
    for (int k = lane; k < 256; k += 32) s += hrow[k] * wr[k];
#pragma unroll
    for (int o = 16; o; o >>= 1) s += __shfl_xor_sync(0xffffffffu, s, o);
    if (lane == 0) out[(t * 4 + b) * 2 + e] = s + woutb[e];
}

// ---------------- launch ----------------
extern "C" void kernel_launch(void* const* d_in, const int* in_sizes, int n_in,
                              void* d_out, int out_size) {
    const float* cam    = (const float*)d_in[0];
    const float* convw  = (const float*)d_in[1];
    const float* convb  = (const float*)d_in[2];
    const float* gamma  = (const float*)d_in[3];
    const float* beta   = (const float*)d_in[4];
    const float* ihw    = (const float*)d_in[5];
    const float* ihb    = (const float*)d_in[6];
    const float* icw    = (const float*)d_in[7];
    const float* icb    = (const float*)d_in[8];
    const float* ww     = (const float*)d_in[9];
    const float* wb     = (const float*)d_in[10];
    const float* wattnw = (const float*)d_in[11];
    // d_in[12] = wattn_b : drops out of softmax/log_softmax (shift-invariant)
    const float* wih    = (const float*)d_in[13];
    const float* whh    = (const float*)d_in[14];
    const float* bih    = (const float*)d_in[15];
    const float* bhh    = (const float*)d_in[16];
    const float* woutw  = (const float*)d_in[17];
    const float* woutb  = (const float*)d_in[18];
    float* out = (float*)d_out;

    aprep_kernel<<<2304, 256>>>(convw);
    convmma_kernel<<<NF * 2, 256>>>(cam, convb);
    stats_kernel<<<ND, 256>>>(gamma, beta);
    attn_kernel<<<NF, 256>>>(wattnw, out);
    init_kernel<<<NB, 256>>>(ihw, ihb, icw, icb);
    weff_kernel<<<ND, 256>>>(wih, ww, whh);
    g1_kernel<<<NF, 1024>>>(wih, wb, bih, bhh);
    for (int t = 0; t < NT; t++)
        step_kernel<<<NB, 1024>>>(t);
    preds_kernel<<<NT, 256>>>(woutw, woutb, out);
}